// round 2
// baseline (speedup 1.0000x reference)
#include <cuda_runtime.h>
#include <cuda_bf16.h>

// Problem constants (from reference)
#define BATCH 1024
#define DDIM  512
#define FDIM  4096
// NNZ = 10,000,000 (read from in_sizes at launch)

// out[b*D+d] = bias[d] + mask[b*D+d], vectorized float4, grid-stride.
__global__ __launch_bounds__(256)
void tied_init_kernel(float4* __restrict__ out4,
                      const float4* __restrict__ bias4,
                      const float4* __restrict__ mask4,
                      int total4) {
    for (int i = blockIdx.x * blockDim.x + threadIdx.x; i < total4;
         i += gridDim.x * blockDim.x) {
        float4 m = mask4[i];
        float4 bv = bias4[i & (DDIM / 4 - 1)];   // D/4 = 128, power of 2
        m.x += bv.x; m.y += bv.y; m.z += bv.z; m.w += bv.w;
        out4[i] = m;
    }
}

// One iteration handles 4 nnz via 128-bit loads; scatter via fire-and-forget
// atomicAdd (REDG) into the L2-resident 2MB output. Grid-stride so all index
// streams stay coalesced and the grid fits in ~1-2 waves.
__global__ __launch_bounds__(256)
void tied_scatter_kernel(const float4* __restrict__ vals4,
                         const int4* __restrict__ b4,
                         const int4* __restrict__ d4,
                         const int4* __restrict__ f4,
                         const float* __restrict__ w,
                         float* __restrict__ out,
                         int n4) {
    for (int i = blockIdx.x * blockDim.x + threadIdx.x; i < n4;
         i += gridDim.x * blockDim.x) {
        float4 v = vals4[i];
        int4 bi = b4[i];
        int4 di = d4[i];
        int4 fi = f4[i];

        // weight gathers: 16KB table, L1-resident after first wave
        float w0 = __ldg(&w[fi.x]);
        float w1 = __ldg(&w[fi.y]);
        float w2 = __ldg(&w[fi.z]);
        float w3 = __ldg(&w[fi.w]);

        atomicAdd(&out[bi.x * DDIM + di.x], v.x * w0);
        atomicAdd(&out[bi.y * DDIM + di.y], v.y * w1);
        atomicAdd(&out[bi.z * DDIM + di.z], v.z * w2);
        atomicAdd(&out[bi.w * DDIM + di.w], v.w * w3);
    }
}

// Tail handler for NNZ not divisible by 4 (defensive; NNZ=10M is divisible).
__global__ __launch_bounds__(256)
void tied_scatter_tail_kernel(const float* __restrict__ vals,
                              const int* __restrict__ b,
                              const int* __restrict__ d,
                              const int* __restrict__ f,
                              const float* __restrict__ w,
                              float* __restrict__ out,
                              int start, int n) {
    int i = start + blockIdx.x * blockDim.x + threadIdx.x;
    if (i >= n) return;
    atomicAdd(&out[b[i] * DDIM + d[i]], vals[i] * __ldg(&w[f[i]]));
}

extern "C" void kernel_launch(void* const* d_in, const int* in_sizes, int n_in,
                              void* d_out, int out_size) {
    // metadata order: values, b_idx, d_idx, f_idx, weight, bias, mask
    const float* values = (const float*)d_in[0];
    const int*   b_idx  = (const int*)d_in[1];
    const int*   d_idx  = (const int*)d_in[2];
    const int*   f_idx  = (const int*)d_in[3];
    const float* weight = (const float*)d_in[4];
    const float* bias   = (const float*)d_in[5];
    const float* mask   = (const float*)d_in[6];
    float* out = (float*)d_out;

    const int nnz = in_sizes[0];
    const int THREADS = 256;
    const int MAX_BLOCKS = 148 * 8;   // ~1 full-occupancy wave

    // 1) init: out = bias + mask  (out_size = B*D = 524288, /4 = 131072)
    {
        int total4 = out_size / 4;
        int blocks = (total4 + THREADS - 1) / THREADS;
        if (blocks > MAX_BLOCKS) blocks = MAX_BLOCKS;
        tied_init_kernel<<<blocks, THREADS>>>((float4*)out,
                                              (const float4*)bias,
                                              (const float4*)mask,
                                              total4);
    }

    // 2) scatter
    {
        int n4 = nnz / 4;
        int blocks = (n4 + THREADS - 1) / THREADS;
        if (blocks > MAX_BLOCKS) blocks = MAX_BLOCKS;
        tied_scatter_kernel<<<blocks, THREADS>>>((const float4*)values,
                                                 (const int4*)b_idx,
                                                 (const int4*)d_idx,
                                                 (const int4*)f_idx,
                                                 weight, out, n4);
        int tail_start = n4 * 4;
        int tail = nnz - tail_start;
        if (tail > 0) {
            tied_scatter_tail_kernel<<<1, 256>>>(values, b_idx, d_idx, f_idx,
                                                 weight, out, tail_start, nnz);
        }
    }
}

// round 3
// speedup vs baseline: 1.0571x; 1.0571x over previous
#include <cuda_runtime.h>
#include <cuda_bf16.h>

// Problem constants (from reference)
#define BATCH 1024
#define DDIM  512
#define FDIM  4096

// out[b*D+d] = bias[d] + mask[b*D+d], vectorized float4, grid-stride.
__global__ __launch_bounds__(256)
void tied_init_kernel(float4* __restrict__ out4,
                      const float4* __restrict__ bias4,
                      const float4* __restrict__ mask4,
                      int total4) {
    for (int i = blockIdx.x * blockDim.x + threadIdx.x; i < total4;
         i += gridDim.x * blockDim.x) {
        float4 m = mask4[i];
        float4 bv = bias4[i & (DDIM / 4 - 1)];   // D/4 = 128, power of 2
        m.x += bv.x; m.y += bv.y; m.z += bv.z; m.w += bv.w;
        out4[i] = m;
    }
}

// 8 nnz per thread per iteration: two independent float4/int4 chunks whose
// 8 LDG.128s are all issued before any consumer, maximizing per-warp MLP.
// Scatter via fire-and-forget atomicAdd (REDG) into the L2-resident output.
__global__ __launch_bounds__(256)
void tied_scatter_kernel(const float4* __restrict__ vals4,
                         const int4* __restrict__ b4,
                         const int4* __restrict__ d4,
                         const int4* __restrict__ f4,
                         const float* __restrict__ w,
                         float* __restrict__ out,
                         int n4) {
    const int S = gridDim.x * blockDim.x;
    int i = blockIdx.x * blockDim.x + threadIdx.x;

    for (; i < n4; i += 2 * S) {
        const int j = i + S;
        const bool has_j = (j < n4);

        // ---- front-batched loads (up to 8x LDG.128) ----
        float4 v0 = vals4[i];
        int4  bi0 = b4[i];
        int4  di0 = d4[i];
        int4  fi0 = f4[i];

        float4 v1;
        int4  bi1, di1, fi1;
        if (has_j) {
            v1  = vals4[j];
            bi1 = b4[j];
            di1 = d4[j];
            fi1 = f4[j];
        }

        // ---- weight gathers (16KB table, L1-resident) ----
        float w00 = __ldg(&w[fi0.x]);
        float w01 = __ldg(&w[fi0.y]);
        float w02 = __ldg(&w[fi0.z]);
        float w03 = __ldg(&w[fi0.w]);

        atomicAdd(&out[bi0.x * DDIM + di0.x], v0.x * w00);
        atomicAdd(&out[bi0.y * DDIM + di0.y], v0.y * w01);
        atomicAdd(&out[bi0.z * DDIM + di0.z], v0.z * w02);
        atomicAdd(&out[bi0.w * DDIM + di0.w], v0.w * w03);

        if (has_j) {
            float w10 = __ldg(&w[fi1.x]);
            float w11 = __ldg(&w[fi1.y]);
            float w12 = __ldg(&w[fi1.z]);
            float w13 = __ldg(&w[fi1.w]);

            atomicAdd(&out[bi1.x * DDIM + di1.x], v1.x * w10);
            atomicAdd(&out[bi1.y * DDIM + di1.y], v1.y * w11);
            atomicAdd(&out[bi1.z * DDIM + di1.z], v1.z * w12);
            atomicAdd(&out[bi1.w * DDIM + di1.w], v1.w * w13);
        }
    }
}

// Tail handler for NNZ not divisible by 4 (defensive; NNZ=10M is divisible).
__global__ __launch_bounds__(256)
void tied_scatter_tail_kernel(const float* __restrict__ vals,
                              const int* __restrict__ b,
                              const int* __restrict__ d,
                              const int* __restrict__ f,
                              const float* __restrict__ w,
                              float* __restrict__ out,
                              int start, int n) {
    int i = start + blockIdx.x * blockDim.x + threadIdx.x;
    if (i >= n) return;
    atomicAdd(&out[b[i] * DDIM + d[i]], vals[i] * __ldg(&w[f[i]]));
}

extern "C" void kernel_launch(void* const* d_in, const int* in_sizes, int n_in,
                              void* d_out, int out_size) {
    // metadata order: values, b_idx, d_idx, f_idx, weight, bias, mask
    const float* values = (const float*)d_in[0];
    const int*   b_idx  = (const int*)d_in[1];
    const int*   d_idx  = (const int*)d_in[2];
    const int*   f_idx  = (const int*)d_in[3];
    const float* weight = (const float*)d_in[4];
    const float* bias   = (const float*)d_in[5];
    const float* mask   = (const float*)d_in[6];
    float* out = (float*)d_out;

    const int nnz = in_sizes[0];
    const int THREADS = 256;
    const int MAX_BLOCKS = 148 * 8;

    // 1) init: out = bias + mask  (out_size = B*D = 524288, /4 = 131072)
    {
        int total4 = out_size / 4;
        int blocks = (total4 + THREADS - 1) / THREADS;
        if (blocks > MAX_BLOCKS) blocks = MAX_BLOCKS;
        tied_init_kernel<<<blocks, THREADS>>>((float4*)out,
                                              (const float4*)bias,
                                              (const float4*)mask,
                                              total4);
    }

    // 2) scatter
    {
        int n4 = nnz / 4;
        int blocks = (n4 + THREADS - 1) / THREADS;
        if (blocks > MAX_BLOCKS) blocks = MAX_BLOCKS;
        tied_scatter_kernel<<<blocks, THREADS>>>((const float4*)values,
                                                 (const int4*)b_idx,
                                                 (const int4*)d_idx,
                                                 (const int4*)f_idx,
                                                 weight, out, n4);
        int tail_start = n4 * 4;
        int tail = nnz - tail_start;
        if (tail > 0) {
            tied_scatter_tail_kernel<<<1, 256>>>(values, b_idx, d_idx, f_idx,
                                                 weight, out, tail_start, nnz);
        }
    }
}